// round 13
// baseline (speedup 1.0000x reference)
#include <cuda_runtime.h>
#include <cuda_bf16.h>

#define TT 20
#define NIMG 64
#define AMAX 9408
#define NT 1024
#define NBLK 192

__device__ float g_partial[NBLK * 3];
__device__ int g_ticket;

__device__ __forceinline__ float wsum(float v) {
#pragma unroll
    for (int o = 16; o; o >>= 1) v += __shfl_down_sync(0xffffffffu, v, o);
    return v;
}
__device__ __forceinline__ int wsumi(int v) {
#pragma unroll
    for (int o = 16; o; o >>= 1) v += __shfl_down_sync(0xffffffffu, v, o);
    return v;
}

__global__ __launch_bounds__(NT, 1) void fused_loss(
    const float* __restrict__ p0, const float* __restrict__ p1, const float* __restrict__ p2,
    const float* __restrict__ tb, const int* __restrict__ tl, float* __restrict__ out)
{
    __shared__ float s_bce[AMAX];
    __shared__ __align__(16) unsigned char s_info[AMAX];   // overlaid as int hist[2048] in mining
    __shared__ float4 sbox[TT];
    __shared__ float sarea[TT];
    __shared__ int slab[TT];
    __shared__ unsigned long long s_best[TT];
    __shared__ unsigned s_aidx[TT];
    __shared__ float s_facc[4];
    __shared__ int s_cnt[4];
    __shared__ int s_ws[32];
    __shared__ int s_selbin, s_Sless;
    __shared__ int s_flag;
    int* const s_hist = reinterpret_cast<int*>(s_info);

    const int bid = blockIdx.x;               // 0..63 s0, 64..127 s1, 128..191 s2
    const int s = (bid < 64) ? 0 : (bid < 128) ? 1 : 2;
    const int b = bid & 63;
    const int f   = 56 >> s;
    const int HW  = f * f;
    const int A   = HW * 3;
    const int shf = 3 - s;                    // f = 7 << shf
    const float strd = (float)(8 << s);
    const float w0 = (float)(16 << s), w1 = (float)(20 << s), w2 = (float)(24 << s);
    const float hmax = (float)(12 << s);      // max anchor half-size at this scale
    const float* pred = ((s == 0) ? p0 : (s == 1) ? p1 : p2) + (size_t)b * 24 * HW;
    const int tid = threadIdx.x;
    const int lane = tid & 31, wid = tid >> 5;

    if (tid < TT) {
        const float* bp = tb + (b * TT + tid) * 4;
        const float4 g = make_float4(bp[0], bp[1], bp[2], bp[3]);
        sbox[tid] = g;
        sarea[tid] = (g.z - g.x) * (g.w - g.y);
        slab[tid] = tl[b * TT + tid];
    }
    if (tid < 4) { s_facc[tid] = 0.f; s_cnt[tid] = 0; }
    __syncthreads();

    // ================= Phase A: per-target best anchor (warp t) ==========
    // Any anchor with IoU > 0 has its center within box +/- hmax. Seed with
    // (iou=0, idx=0) so an all-zero IoU column yields argmax = 0 like jnp.
    if (wid < TT) {
        const int t = wid;
        const float4 g = sbox[t];
        const float ar = sarea[t];
        const float inv = 1.0f / strd;
        const int gx0 = max(0, (int)floorf((g.x - hmax) * inv - 0.5f));
        const int gx1 = min(f - 1, (int)ceilf((g.z + hmax) * inv - 0.5f));
        const int gy0 = max(0, (int)floorf((g.y - hmax) * inv - 0.5f));
        const int gy1 = min(f - 1, (int)ceilf((g.w + hmax) * inv - 0.5f));
        const int rowc = (gx1 - gx0 + 1) * 3;
        const int total = (gy1 - gy0 + 1) * rowc;
        unsigned long long best = (lane == 0) ? 0xFFFFFFFFull : 0ull;
        for (int i = lane; i < total; i += 32) {
            const int r = i / rowc;
            const int rem = i - r * rowc;
            const int cq = rem / 3;
            const int a3 = rem - cq * 3;
            const int gx = gx0 + cq;
            const int gy = gy0 + r;
            const float cx = ((float)gx + 0.5f) * strd;
            const float cy = ((float)gy + 0.5f) * strd;
            const float w = (a3 == 0) ? w0 : (a3 == 1) ? w1 : w2;
            const float h2 = 0.5f * w;
            const float areaA = w * w;
            const float iw = fminf(cx + h2, g.z) - fmaxf(cx - h2, g.x);
            const float ih = fminf(cy + h2, g.w) - fmaxf(cy - h2, g.y);
            const float inter = fmaxf(iw, 0.f) * fmaxf(ih, 0.f);
            const float uni = areaA + ar - inter + 1e-9f;
            const float iou = __fdividef(inter, uni);
            const int aidx = (gy * f + gx) * 3 + a3;
            const unsigned long long pk =
                ((unsigned long long)__float_as_uint(iou) << 32) | (unsigned)(~(unsigned)aidx);
            if (pk > best) best = pk;
        }
#pragma unroll
        for (int o = 16; o; o >>= 1) {
            const unsigned long long u = __shfl_down_sync(0xffffffffu, best, o);
            if (u > best) best = u;
        }
        if (lane == 0) s_best[t] = best;
    }

    // ================= Matching + BCE (no per-target bookkeeping) ========
    for (int base = wid * 32; base < A; base += NT) {
        const int idx = base + lane;
        const bool valid = idx < A;
        const int cidx = valid ? idx : (A - 1);
        const int pix = cidx / 3;
        const int a3  = cidx - pix * 3;
        const int q   = pix >> shf;
        const int gy  = q / 7;
        const int gx  = pix - gy * f;
        const float cx = ((float)gx + 0.5f) * strd;
        const float cy = ((float)gy + 0.5f) * strd;
        const float w  = (a3 == 0) ? w0 : (a3 == 1) ? w1 : w2;
        const float h2 = 0.5f * w;
        const float ax1 = cx - h2, ay1 = cy - h2, ax2 = cx + h2, ay2 = cy + h2;
        const float areaA = w * w;

        // analytic warp bounding band
        const int p_lo = base / 3;
        const int p_hi = min(base + 31, A - 1) / 3;
        const int gy0 = (p_lo >> shf) / 7;
        const int gy1 = (p_hi >> shf) / 7;
        int gx0, gx1;
        if (gy0 == gy1) { gx0 = p_lo - gy0 * f; gx1 = p_hi - gy1 * f; }
        else            { gx0 = 0; gx1 = f - 1; }
        const float xl = ((float)gx0 + 0.5f) * strd - hmax;
        const float xh = ((float)gx1 + 0.5f) * strd + hmax;
        const float yl = ((float)gy0 + 0.5f) * strd - hmax;
        const float yh = ((float)gy1 + 0.5f) * strd + hmax;

        bool act = false;
        if (lane < TT) {
            const float4 g = sbox[lane];
            act = (g.z > xl) && (g.x < xh) && (g.w > yl) && (g.y < yh);
        }
        const unsigned mask = __ballot_sync(0xffffffffu, act);

        float maxiou = 0.f; int mt = 0;
        unsigned m = mask;
        while (m) {                              // ascending t: first-index tie-break
            const int t = __ffs(m) - 1;
            m &= m - 1;
            const float4 g = sbox[t];
            const float iw = fminf(ax2, g.z) - fmaxf(ax1, g.x);
            const float ih = fminf(ay2, g.w) - fmaxf(ay1, g.y);
            const float inter = fmaxf(iw, 0.f) * fmaxf(ih, 0.f);
            const float uni = areaA + sarea[t] - inter + 1e-9f;
            const float iou = __fdividef(inter, uni);
            if (iou > maxiou) { maxiou = iou; mt = t; }
        }
        if (valid) {
            unsigned info = (unsigned)mt;
            const bool pos = maxiou >= 0.5f;
            if (pos) info |= 64u;
            if (maxiou < 0.3f) info |= 128u;
            const float x = __ldg(pred + (a3 * 8 + 4) * HW + pix);
            const float bce = fmaxf(x, 0.f) - (pos ? x : 0.f) + log1pf(__expf(-fabsf(x)));
            s_bce[idx]  = bce;
            s_info[idx] = (unsigned char)info;
        }
    }
    __syncthreads();

    // ================= Forced-match overrides (parallel, last-t wins) ====
    if (wid == 0) {
        const bool has = lane < TT;
        unsigned aidx = 0;
        if (has) {
            const unsigned long long v = s_best[lane];
            aidx = ~(unsigned)(v & 0xFFFFFFFFull);
            s_aidx[lane] = aidx;
        }
        __syncwarp();
        bool win = has;
        if (has) {
            for (int t2 = lane + 1; t2 < TT; t2++)
                if (s_aidx[t2] == aidx) win = false;
        }
        if (win) {
            const unsigned old = s_info[aidx];
            if (!(old & 64u)) {                 // newly positive: bce(y=0) -> bce(y=1)
                const int pix = aidx / 3, a3 = aidx - pix * 3;
                s_bce[aidx] -= __ldg(pred + (a3 * 8 + 4) * HW + pix);
            }
            s_info[aidx] = (unsigned char)(lane | 64u);
        }
    }
    __syncthreads();

    // ================= Epilogue: counts, CE + smooth-L1 on positives =====
    // Clobber non-negative keys to 0 so mining needs only s_bce.
    float pos_bce = 0.f, cls_sum = 0.f, loc_sum = 0.f;
    int pos_cnt = 0, neg_cnt = 0;
    for (int idx = tid; idx < A; idx += NT) {
        const unsigned info = s_info[idx];
        if (info & 128u) neg_cnt++;
        else {
            const float bv = s_bce[idx];
            s_bce[idx] = 0.0f;
            if (info & 64u) {
                pos_cnt++;
                pos_bce += bv;
                const int mt = info & 31u;
                const int pix = idx / 3, a3 = idx - pix * 3;
                const float* pp = pred + a3 * 8 * HW + pix;
                const float c0 = pp[5 * HW], c1 = pp[6 * HW], c2 = pp[7 * HW];
                const float m = fmaxf(c0, fmaxf(c1, c2));
                const float lse = m + __logf(__expf(c0 - m) + __expf(c1 - m) + __expf(c2 - m));
                const int tgt = slab[mt] - 1;
                const float ct = (tgt == 0) ? c0 : (tgt == 1) ? c1 : c2;
                cls_sum += lse - ct;

                const int q = pix >> shf;
                const int gy = q / 7;
                const int gx = pix - gy * f;
                const float cx = ((float)gx + 0.5f) * strd;
                const float cy = ((float)gy + 0.5f) * strd;
                const float w = (a3 == 0) ? w0 : (a3 == 1) ? w1 : w2;
                const float4 g = sbox[mt];
                const float gw = g.z - g.x, gh = g.w - g.y;
                const float gcx = (g.x + g.z) * 0.5f, gcy = (g.y + g.w) * 0.5f;
                const float td0 = __fdividef(gcx - cx, w);
                const float td1 = __fdividef(gcy - cy, w);
                const float td2 = __logf(__fdividef(gw, w));
                const float td3 = __logf(__fdividef(gh, w));
                const float d0 = fabsf(pp[0 * HW] - td0);
                const float d1 = fabsf(pp[1 * HW] - td1);
                const float d2 = fabsf(pp[2 * HW] - td2);
                const float d3 = fabsf(pp[3 * HW] - td3);
                loc_sum += (d0 < 1.f ? 0.5f * d0 * d0 : d0 - 0.5f)
                         + (d1 < 1.f ? 0.5f * d1 * d1 : d1 - 0.5f)
                         + (d2 < 1.f ? 0.5f * d2 * d2 : d2 - 0.5f)
                         + (d3 < 1.f ? 0.5f * d3 * d3 : d3 - 0.5f);
            }
        }
    }
    pos_bce = wsum(pos_bce); cls_sum = wsum(cls_sum); loc_sum = wsum(loc_sum);
    pos_cnt = wsumi(pos_cnt); neg_cnt = wsumi(neg_cnt);
    if (lane == 0) {
        atomicAdd(&s_facc[0], pos_bce);
        atomicAdd(&s_facc[1], cls_sum);
        atomicAdd(&s_facc[2], loc_sum);
        atomicAdd(&s_cnt[0], pos_cnt);
        atomicAdd(&s_cnt[1], neg_cnt);
    }
    __syncthreads();
    const int num_pos = s_cnt[0];
    const int num_neg = s_cnt[1];
    const int need = min(3 * num_pos, num_neg);

    // ================= 3-pass radix select (need-th largest key) =========
    float neg_sum = 0.f;
    if (need > 0) {
        int kneed = need;
        unsigned prefix = 0;
        const int shv[3] = {21, 10, 0};
        const int wv[3]  = {11, 11, 10};
#pragma unroll
        for (int p = 0; p < 3; p++) {
            const int sh = shv[p], w = wv[p];
            const int nb = 1 << w;              // 2048, 2048, 1024
            const int gpt = (nb + NT - 1) / NT; // 2, 2, 1
            for (int i = tid; i < nb; i += NT) s_hist[i] = 0;
            __syncthreads();
            for (int idx = tid; idx < A; idx += NT) {
                const unsigned bits = __float_as_uint(s_bce[idx]);
                if (p == 0 || (bits >> (sh + w)) == prefix)
                    atomicAdd(&s_hist[(bits >> sh) & (nb - 1)], 1);
            }
            __syncthreads();
            const int bbase = tid * gpt;
            int h[2]; int local = 0;
#pragma unroll
            for (int j = 0; j < 2; j++) {
                h[j] = (j < gpt && bbase + j < nb) ? s_hist[bbase + j] : 0;
                local += h[j];
            }
            int v = local;                       // inclusive suffix within warp
#pragma unroll
            for (int o = 1; o < 32; o <<= 1) {
                const int u = __shfl_down_sync(0xffffffffu, v, o);
                if (lane + o < 32) v += u;
            }
            if (lane == 0) s_ws[wid] = v;
            __syncthreads();
            if (tid < 32) {
                int x = s_ws[tid];
#pragma unroll
                for (int o = 1; o < 32; o <<= 1) {
                    const int u = __shfl_down_sync(0xffffffffu, x, o);
                    if (tid + o < 32) x += u;
                }
                s_ws[tid] = x;                   // inclusive suffix of warp sums
            }
            __syncthreads();
            int suf = (v - local) + ((wid < 31) ? s_ws[wid + 1] : 0);
#pragma unroll
            for (int j = 1; j >= 0; j--) {
                if (j < gpt && bbase + j < nb) {
                    if (suf < kneed && kneed <= suf + h[j]) { s_selbin = bbase + j; s_Sless = suf; }
                    suf += h[j];
                }
            }
            __syncthreads();
            kneed -= s_Sless;
            prefix = (prefix << w) | (unsigned)s_selbin;
            __syncthreads();
        }
        const unsigned kbits = prefix;           // bits of the need-th largest key
        int cgt = 0; float sgt = 0.f;
        for (int idx = tid; idx < A; idx += NT) {
            const float vv = s_bce[idx];
            if (__float_as_uint(vv) > kbits) { cgt++; sgt += vv; }
        }
        cgt = wsumi(cgt); sgt = wsum(sgt);
        if (lane == 0) { atomicAdd(&s_cnt[2], cgt); atomicAdd(&s_facc[3], sgt); }
        __syncthreads();
        neg_sum = s_facc[3] + (float)(need - s_cnt[2]) * __uint_as_float(kbits);
    }

    if (tid == 0) {
        const float obj_loss = (s_facc[0] + neg_sum) / (float)max(num_pos + need, 1);
        const float cls_loss = s_facc[1] / (float)max(num_pos, 1);
        const float loc_loss = s_facc[2] / (float)max(4 * num_pos, 1);
        g_partial[bid * 3 + 0] = obj_loss;
        g_partial[bid * 3 + 1] = cls_loss;
        g_partial[bid * 3 + 2] = loc_loss;
    }

    // ================= Last-block finalize ================================
    __threadfence();
    if (tid == 0) {
        const int t = atomicAdd(&g_ticket, 1);
        s_flag = (t == NBLK - 1);
    }
    __syncthreads();
    if (s_flag && tid < 32) {
        float o = 0.f, c = 0.f, l = 0.f;
        for (int i = tid; i < NBLK; i += 32) {
            o += g_partial[3 * i + 0];
            c += g_partial[3 * i + 1];
            l += g_partial[3 * i + 2];
        }
        o = wsum(o); c = wsum(c); l = wsum(l);
        if (tid == 0) {
            g_ticket = 0;                        // self-reset for next replay
            o *= (1.f / 64.f); c *= (1.f / 64.f); l *= (1.f / 64.f);
            out[0] = o; out[1] = c; out[2] = l; out[3] = o + c + 2.f * l;
        }
    }
}

extern "C" void kernel_launch(void* const* d_in, const int* in_sizes, int n_in,
                              void* d_out, int out_size) {
    const float* p0 = (const float*)d_in[0];
    const float* p1 = (const float*)d_in[1];
    const float* p2 = (const float*)d_in[2];
    const float* tb = (const float*)d_in[6];
    const int*   tl = (const int*)d_in[7];

    fused_loss<<<NBLK, NT>>>(p0, p1, p2, tb, tl, (float*)d_out);
}

// round 14
// speedup vs baseline: 1.4389x; 1.4389x over previous
#include <cuda_runtime.h>
#include <cuda_bf16.h>

#define TT 20
#define NIMG 64
#define AMAX 9408
#define NT 1024
#define NBLK 192
#define NBATCH ((AMAX + 31) / 32)

__device__ float g_partial[NBLK * 3];
__device__ int g_ticket;

__device__ __forceinline__ float wsum(float v) {
#pragma unroll
    for (int o = 16; o; o >>= 1) v += __shfl_down_sync(0xffffffffu, v, o);
    return v;
}
__device__ __forceinline__ int wsumi(int v) {
#pragma unroll
    for (int o = 16; o; o >>= 1) v += __shfl_down_sync(0xffffffffu, v, o);
    return v;
}

__global__ __launch_bounds__(NT, 1) void fused_loss(
    const float* __restrict__ p0, const float* __restrict__ p1, const float* __restrict__ p2,
    const float* __restrict__ tb, const int* __restrict__ tl, float* __restrict__ out)
{
    __shared__ float s_bce[AMAX];
    __shared__ __align__(16) unsigned char s_info[AMAX];   // overlaid as int hist[2048] in mining
    __shared__ int s_tmask[NBATCH];
    __shared__ float4 sbox[TT];
    __shared__ float sarea[TT];
    __shared__ int slab[TT];
    __shared__ unsigned long long s_best[TT];
    __shared__ unsigned s_aidx[TT];
    __shared__ float s_facc[4];
    __shared__ int s_cnt[4];
    __shared__ int s_ws[32];
    __shared__ int s_selbin, s_Sless;
    __shared__ int s_flag;
    int* const s_hist = reinterpret_cast<int*>(s_info);

    const int bid = blockIdx.x;               // 0..63 s0, 64..127 s1, 128..191 s2
    const int s = (bid < 64) ? 0 : (bid < 128) ? 1 : 2;
    const int b = bid & 63;
    const int f   = 56 >> s;
    const int HW  = f * f;
    const int A   = HW * 3;
    const int shf = 3 - s;                    // f = 7 << shf
    const float strd = (float)(8 << s);
    const float w0 = (float)(16 << s), w1 = (float)(20 << s), w2 = (float)(24 << s);
    const float hmax = (float)(12 << s);      // max anchor half-size at this scale
    const float* pred = ((s == 0) ? p0 : (s == 1) ? p1 : p2) + (size_t)b * 24 * HW;
    const int tid = threadIdx.x;
    const int lane = tid & 31, wid = tid >> 5;
    const int nbatch = (A + 31) >> 5;

    if (tid < TT) {
        const float* bp = tb + (b * TT + tid) * 4;
        const float4 g = make_float4(bp[0], bp[1], bp[2], bp[3]);
        sbox[tid] = g;
        sarea[tid] = (g.z - g.x) * (g.w - g.y);
        slab[tid] = tl[b * TT + tid];
    }
    if (tid < 4) { s_facc[tid] = 0.f; s_cnt[tid] = 0; }
    __syncthreads();

    // ========== Precompute per-batch target masks (one thread/batch) =====
    if (tid < nbatch) {
        const int base = tid << 5;
        const int p_lo = base / 3;
        const int p_hi = min(base + 31, A - 1) / 3;
        const int gy0 = (p_lo >> shf) / 7;
        const int gy1 = (p_hi >> shf) / 7;
        int gx0, gx1;
        if (gy0 == gy1) { gx0 = p_lo - gy0 * f; gx1 = p_hi - gy1 * f; }
        else            { gx0 = 0; gx1 = f - 1; }
        const float xl = ((float)gx0 + 0.5f) * strd - hmax;
        const float xh = ((float)gx1 + 0.5f) * strd + hmax;
        const float yl = ((float)gy0 + 0.5f) * strd - hmax;
        const float yh = ((float)gy1 + 0.5f) * strd + hmax;
        unsigned msk = 0;
#pragma unroll
        for (int t = 0; t < TT; t++) {
            const float4 g = sbox[t];
            if ((g.z > xl) && (g.x < xh) && (g.w > yl) && (g.y < yh)) msk |= 1u << t;
        }
        s_tmask[tid] = (int)msk;
    }
    __syncthreads();

    // ================= Phase A: per-target best anchor (warp t) ==========
    // Any anchor with IoU > 0 has its center within box +/- hmax. Seed with
    // (iou=0, idx=0) so an all-zero IoU column yields argmax = 0 like jnp.
    if (wid < TT) {
        const int t = wid;
        const float4 g = sbox[t];
        const float ar = sarea[t];
        const float inv = 1.0f / strd;
        const int gx0 = max(0, (int)floorf((g.x - hmax) * inv - 0.5f));
        const int gx1 = min(f - 1, (int)ceilf((g.z + hmax) * inv - 0.5f));
        const int gy0 = max(0, (int)floorf((g.y - hmax) * inv - 0.5f));
        const int gy1 = min(f - 1, (int)ceilf((g.w + hmax) * inv - 0.5f));
        const int rowc = (gx1 - gx0 + 1) * 3;
        const int total = (gy1 - gy0 + 1) * rowc;
        unsigned long long best = (lane == 0) ? 0xFFFFFFFFull : 0ull;
        for (int i = lane; i < total; i += 32) {
            const int r = i / rowc;
            const int rem = i - r * rowc;
            const int cq = rem / 3;
            const int a3 = rem - cq * 3;
            const int gx = gx0 + cq;
            const int gy = gy0 + r;
            const float cx = ((float)gx + 0.5f) * strd;
            const float cy = ((float)gy + 0.5f) * strd;
            const float w = (a3 == 0) ? w0 : (a3 == 1) ? w1 : w2;
            const float h2 = 0.5f * w;
            const float areaA = w * w;
            const float iw = fminf(cx + h2, g.z) - fmaxf(cx - h2, g.x);
            const float ih = fminf(cy + h2, g.w) - fmaxf(cy - h2, g.y);
            const float inter = fmaxf(iw, 0.f) * fmaxf(ih, 0.f);
            const float uni = areaA + ar - inter + 1e-9f;
            const float iou = __fdividef(inter, uni);
            const int aidx = (gy * f + gx) * 3 + a3;
            const unsigned long long pk =
                ((unsigned long long)__float_as_uint(iou) << 32) | (unsigned)(~(unsigned)aidx);
            if (pk > best) best = pk;
        }
#pragma unroll
        for (int o = 16; o; o >>= 1) {
            const unsigned long long u = __shfl_down_sync(0xffffffffu, best, o);
            if (u > best) best = u;
        }
        if (lane == 0) s_best[t] = best;
    }

    // ================= Matching + BCE (mask lookup, unrolled inner) ======
    for (int base = wid * 32; base < A; base += NT) {
        const int idx = base + lane;
        const bool valid = idx < A;
        const int cidx = valid ? idx : (A - 1);
        const int pix = cidx / 3;
        const int a3  = cidx - pix * 3;
        const int q   = pix >> shf;
        const int gy  = q / 7;
        const int gx  = pix - gy * f;
        const float cx = ((float)gx + 0.5f) * strd;
        const float cy = ((float)gy + 0.5f) * strd;
        const float w  = (a3 == 0) ? w0 : (a3 == 1) ? w1 : w2;
        const float h2 = 0.5f * w;
        const float ax1 = cx - h2, ay1 = cy - h2, ax2 = cx + h2, ay2 = cy + h2;
        const float areaA = w * w;

        const unsigned mask = (unsigned)s_tmask[base >> 5];

        float maxiou = 0.f; int mt = 0;
        if (mask) {
#pragma unroll
            for (int t = 0; t < TT; t++) {
                if (mask & (1u << t)) {
                    const float4 g = sbox[t];
                    const float iw = fminf(ax2, g.z) - fmaxf(ax1, g.x);
                    const float ih = fminf(ay2, g.w) - fmaxf(ay1, g.y);
                    const float inter = fmaxf(iw, 0.f) * fmaxf(ih, 0.f);
                    const float uni = areaA + sarea[t] - inter + 1e-9f;
                    const float iou = __fdividef(inter, uni);
                    if (iou > maxiou) { maxiou = iou; mt = t; }   // first-index tie-break
                }
            }
        }
        if (valid) {
            unsigned info = (unsigned)mt;
            const bool pos = maxiou >= 0.5f;
            if (pos) info |= 64u;
            if (maxiou < 0.3f) info |= 128u;
            const float x = __ldg(pred + (a3 * 8 + 4) * HW + pix);
            const float bce = fmaxf(x, 0.f) - (pos ? x : 0.f) + __logf(1.f + __expf(-fabsf(x)));
            s_bce[idx]  = bce;
            s_info[idx] = (unsigned char)info;
        }
    }
    __syncthreads();

    // ================= Forced-match overrides (parallel, last-t wins) ====
    if (wid == 0) {
        const bool has = lane < TT;
        unsigned aidx = 0;
        if (has) {
            const unsigned long long v = s_best[lane];
            aidx = ~(unsigned)(v & 0xFFFFFFFFull);
            s_aidx[lane] = aidx;
        }
        __syncwarp();
        bool win = has;
        if (has) {
            for (int t2 = lane + 1; t2 < TT; t2++)
                if (s_aidx[t2] == aidx) win = false;
        }
        if (win) {
            const unsigned old = s_info[aidx];
            if (!(old & 64u)) {                 // newly positive: bce(y=0) -> bce(y=1)
                const int pix = aidx / 3, a3 = aidx - pix * 3;
                s_bce[aidx] -= __ldg(pred + (a3 * 8 + 4) * HW + pix);
            }
            s_info[aidx] = (unsigned char)(lane | 64u);
        }
    }
    __syncthreads();

    // ================= Epilogue: counts, CE + smooth-L1 on positives =====
    // Clobber non-negative keys to 0 so mining needs only s_bce.
    float pos_bce = 0.f, cls_sum = 0.f, loc_sum = 0.f;
    int pos_cnt = 0, neg_cnt = 0;
    for (int idx = tid; idx < A; idx += NT) {
        const unsigned info = s_info[idx];
        if (info & 128u) neg_cnt++;
        else {
            const float bv = s_bce[idx];
            s_bce[idx] = 0.0f;
            if (info & 64u) {
                pos_cnt++;
                pos_bce += bv;
                const int mt = info & 31u;
                const int pix = idx / 3, a3 = idx - pix * 3;
                const float* pp = pred + a3 * 8 * HW + pix;
                const float c0 = pp[5 * HW], c1 = pp[6 * HW], c2 = pp[7 * HW];
                const float m = fmaxf(c0, fmaxf(c1, c2));
                const float lse = m + __logf(__expf(c0 - m) + __expf(c1 - m) + __expf(c2 - m));
                const int tgt = slab[mt] - 1;
                const float ct = (tgt == 0) ? c0 : (tgt == 1) ? c1 : c2;
                cls_sum += lse - ct;

                const int q = pix >> shf;
                const int gy = q / 7;
                const int gx = pix - gy * f;
                const float cx = ((float)gx + 0.5f) * strd;
                const float cy = ((float)gy + 0.5f) * strd;
                const float w = (a3 == 0) ? w0 : (a3 == 1) ? w1 : w2;
                const float4 g = sbox[mt];
                const float gw = g.z - g.x, gh = g.w - g.y;
                const float gcx = (g.x + g.z) * 0.5f, gcy = (g.y + g.w) * 0.5f;
                const float td0 = __fdividef(gcx - cx, w);
                const float td1 = __fdividef(gcy - cy, w);
                const float td2 = __logf(__fdividef(gw, w));
                const float td3 = __logf(__fdividef(gh, w));
                const float d0 = fabsf(pp[0 * HW] - td0);
                const float d1 = fabsf(pp[1 * HW] - td1);
                const float d2 = fabsf(pp[2 * HW] - td2);
                const float d3 = fabsf(pp[3 * HW] - td3);
                loc_sum += (d0 < 1.f ? 0.5f * d0 * d0 : d0 - 0.5f)
                         + (d1 < 1.f ? 0.5f * d1 * d1 : d1 - 0.5f)
                         + (d2 < 1.f ? 0.5f * d2 * d2 : d2 - 0.5f)
                         + (d3 < 1.f ? 0.5f * d3 * d3 : d3 - 0.5f);
            }
        }
    }
    pos_bce = wsum(pos_bce); cls_sum = wsum(cls_sum); loc_sum = wsum(loc_sum);
    pos_cnt = wsumi(pos_cnt); neg_cnt = wsumi(neg_cnt);
    if (lane == 0) {
        atomicAdd(&s_facc[0], pos_bce);
        atomicAdd(&s_facc[1], cls_sum);
        atomicAdd(&s_facc[2], loc_sum);
        atomicAdd(&s_cnt[0], pos_cnt);
        atomicAdd(&s_cnt[1], neg_cnt);
    }
    __syncthreads();
    const int num_pos = s_cnt[0];
    const int num_neg = s_cnt[1];
    const int need = min(3 * num_pos, num_neg);

    // ================= 3-pass radix select (need-th largest key) =========
    float neg_sum = 0.f;
    if (need > 0) {
        int kneed = need;
        unsigned prefix = 0;
        const int shv[3] = {21, 10, 0};
        const int wv[3]  = {11, 11, 10};
#pragma unroll
        for (int p = 0; p < 3; p++) {
            const int sh = shv[p], w = wv[p];
            const int nb = 1 << w;              // 2048, 2048, 1024
            const int gpt = (nb + NT - 1) / NT; // 2, 2, 1
            for (int i = tid; i < nb; i += NT) s_hist[i] = 0;
            __syncthreads();
            for (int idx = tid; idx < A; idx += NT) {
                const unsigned bits = __float_as_uint(s_bce[idx]);
                if (p == 0 || (bits >> (sh + w)) == prefix)
                    atomicAdd(&s_hist[(bits >> sh) & (nb - 1)], 1);
            }
            __syncthreads();
            const int bbase = tid * gpt;
            int h[2]; int local = 0;
#pragma unroll
            for (int j = 0; j < 2; j++) {
                h[j] = (j < gpt && bbase + j < nb) ? s_hist[bbase + j] : 0;
                local += h[j];
            }
            int v = local;                       // inclusive suffix within warp
#pragma unroll
            for (int o = 1; o < 32; o <<= 1) {
                const int u = __shfl_down_sync(0xffffffffu, v, o);
                if (lane + o < 32) v += u;
            }
            if (lane == 0) s_ws[wid] = v;
            __syncthreads();
            if (tid < 32) {
                int x = s_ws[tid];
#pragma unroll
                for (int o = 1; o < 32; o <<= 1) {
                    const int u = __shfl_down_sync(0xffffffffu, x, o);
                    if (tid + o < 32) x += u;
                }
                s_ws[tid] = x;                   // inclusive suffix of warp sums
            }
            __syncthreads();
            int suf = (v - local) + ((wid < 31) ? s_ws[wid + 1] : 0);
#pragma unroll
            for (int j = 1; j >= 0; j--) {
                if (j < gpt && bbase + j < nb) {
                    if (suf < kneed && kneed <= suf + h[j]) { s_selbin = bbase + j; s_Sless = suf; }
                    suf += h[j];
                }
            }
            __syncthreads();
            kneed -= s_Sless;
            prefix = (prefix << w) | (unsigned)s_selbin;
            __syncthreads();
        }
        const unsigned kbits = prefix;           // bits of the need-th largest key
        int cgt = 0; float sgt = 0.f;
        for (int idx = tid; idx < A; idx += NT) {
            const float vv = s_bce[idx];
            if (__float_as_uint(vv) > kbits) { cgt++; sgt += vv; }
        }
        cgt = wsumi(cgt); sgt = wsum(sgt);
        if (lane == 0) { atomicAdd(&s_cnt[2], cgt); atomicAdd(&s_facc[3], sgt); }
        __syncthreads();
        neg_sum = s_facc[3] + (float)(need - s_cnt[2]) * __uint_as_float(kbits);
    }

    if (tid == 0) {
        const float obj_loss = (s_facc[0] + neg_sum) / (float)max(num_pos + need, 1);
        const float cls_loss = s_facc[1] / (float)max(num_pos, 1);
        const float loc_loss = s_facc[2] / (float)max(4 * num_pos, 1);
        g_partial[bid * 3 + 0] = obj_loss;
        g_partial[bid * 3 + 1] = cls_loss;
        g_partial[bid * 3 + 2] = loc_loss;
    }

    // ================= Last-block finalize ================================
    __threadfence();
    if (tid == 0) {
        const int t = atomicAdd(&g_ticket, 1);
        s_flag = (t == NBLK - 1);
    }
    __syncthreads();
    if (s_flag && tid < 32) {
        float o = 0.f, c = 0.f, l = 0.f;
        for (int i = tid; i < NBLK; i += 32) {
            o += g_partial[3 * i + 0];
            c += g_partial[3 * i + 1];
            l += g_partial[3 * i + 2];
        }
        o = wsum(o); c = wsum(c); l = wsum(l);
        if (tid == 0) {
            g_ticket = 0;                        // self-reset for next replay
            o *= (1.f / 64.f); c *= (1.f / 64.f); l *= (1.f / 64.f);
            out[0] = o; out[1] = c; out[2] = l; out[3] = o + c + 2.f * l;
        }
    }
}

extern "C" void kernel_launch(void* const* d_in, const int* in_sizes, int n_in,
                              void* d_out, int out_size) {
    const float* p0 = (const float*)d_in[0];
    const float* p1 = (const float*)d_in[1];
    const float* p2 = (const float*)d_in[2];
    const float* tb = (const float*)d_in[6];
    const int*   tl = (const int*)d_in[7];

    fused_loss<<<NBLK, NT>>>(p0, p1, p2, tb, tl, (float*)d_out);
}

// round 15
// speedup vs baseline: 1.6411x; 1.1405x over previous
#include <cuda_runtime.h>
#include <cuda_bf16.h>

#define TT 20
#define NIMG 64
#define AMAX 9408
#define NT 1024
#define NBLK 192
#define NBATCH ((AMAX + 31) / 32)

__device__ float g_partial[NBLK * 3];
__device__ int g_ticket;

__device__ __forceinline__ float wsum(float v) {
#pragma unroll
    for (int o = 16; o; o >>= 1) v += __shfl_down_sync(0xffffffffu, v, o);
    return v;
}
__device__ __forceinline__ int wsumi(int v) {
#pragma unroll
    for (int o = 16; o; o >>= 1) v += __shfl_down_sync(0xffffffffu, v, o);
    return v;
}

__global__ __launch_bounds__(NT, 1) void fused_loss(
    const float* __restrict__ p0, const float* __restrict__ p1, const float* __restrict__ p2,
    const float* __restrict__ tb, const int* __restrict__ tl, float* __restrict__ out)
{
    __shared__ float s_bce[AMAX];
    __shared__ __align__(16) unsigned char s_info[AMAX];   // overlaid as int hist[2048] in mining
    __shared__ int s_tmask[NBATCH];
    __shared__ float4 sbox[TT];
    __shared__ float sarea[TT];
    __shared__ int slab[TT];
    __shared__ unsigned long long s_best[TT];
    __shared__ unsigned s_aidx[TT];
    __shared__ float s_facc[4];
    __shared__ int s_cnt[4];
    __shared__ int s_ws[32];
    __shared__ int s_selbin, s_Sless;
    __shared__ int s_flag;
    int* const s_hist = reinterpret_cast<int*>(s_info);

    const int bid = blockIdx.x;               // 0..63 s0, 64..127 s1, 128..191 s2
    const int s = (bid < 64) ? 0 : (bid < 128) ? 1 : 2;
    const int b = bid & 63;
    const int f   = 56 >> s;
    const int HW  = f * f;
    const int A   = HW * 3;
    const int shf = 3 - s;                    // f = 7 << shf
    const float strd = (float)(8 << s);
    const float w0 = (float)(16 << s), w1 = (float)(20 << s), w2 = (float)(24 << s);
    const float hmax = (float)(12 << s);      // max anchor half-size at this scale
    const float* pred = ((s == 0) ? p0 : (s == 1) ? p1 : p2) + (size_t)b * 24 * HW;
    const int tid = threadIdx.x;
    const int lane = tid & 31, wid = tid >> 5;
    const int nbatch = (A + 31) >> 5;

    if (tid < TT) {
        const float* bp = tb + (b * TT + tid) * 4;
        const float4 g = make_float4(bp[0], bp[1], bp[2], bp[3]);
        sbox[tid] = g;
        sarea[tid] = (g.z - g.x) * (g.w - g.y);
        slab[tid] = tl[b * TT + tid];
        // seed = packed (iou=0, anchor 0): all-zero IoU column -> argmax 0,
        // matching jnp.argmax semantics; any positive-IoU key beats it.
        s_best[tid] = 0x00000000FFFFFFFFull;
    }
    if (tid < 4) { s_facc[tid] = 0.f; s_cnt[tid] = 0; }
    __syncthreads();

    // ========== Precompute per-batch target masks (one thread/batch) =====
    if (tid < nbatch) {
        const int base = tid << 5;
        const int p_lo = base / 3;
        const int p_hi = min(base + 31, A - 1) / 3;
        const int gy0 = (p_lo >> shf) / 7;
        const int gy1 = (p_hi >> shf) / 7;
        int gx0, gx1;
        if (gy0 == gy1) { gx0 = p_lo - gy0 * f; gx1 = p_hi - gy1 * f; }
        else            { gx0 = 0; gx1 = f - 1; }
        const float xl = ((float)gx0 + 0.5f) * strd - hmax;
        const float xh = ((float)gx1 + 0.5f) * strd + hmax;
        const float yl = ((float)gy0 + 0.5f) * strd - hmax;
        const float yh = ((float)gy1 + 0.5f) * strd + hmax;
        unsigned msk = 0;
#pragma unroll
        for (int t = 0; t < TT; t++) {
            const float4 g = sbox[t];
            if ((g.z > xl) && (g.x < xh) && (g.w > yl) && (g.y < yh)) msk |= 1u << t;
        }
        s_tmask[tid] = (int)msk;
    }
    __syncthreads();

    // ===== Matching + BCE (mask lookup + inline per-target best) =========
    for (int base = wid * 32; base < A; base += NT) {
        const int idx = base + lane;
        const bool valid = idx < A;
        const int cidx = valid ? idx : (A - 1);
        const int pix = cidx / 3;
        const int a3  = cidx - pix * 3;
        const int q   = pix >> shf;
        const int gy  = q / 7;
        const int gx  = pix - gy * f;
        const float cx = ((float)gx + 0.5f) * strd;
        const float cy = ((float)gy + 0.5f) * strd;
        const float w  = (a3 == 0) ? w0 : (a3 == 1) ? w1 : w2;
        const float h2 = 0.5f * w;
        const float ax1 = cx - h2, ay1 = cy - h2, ax2 = cx + h2, ay2 = cy + h2;
        const float areaA = w * w;

        const unsigned mask = (unsigned)s_tmask[base >> 5];

        float maxiou = 0.f; int mt = 0;
        const unsigned nidx = ~(unsigned)cidx;
        if (mask) {
#pragma unroll
            for (int t = 0; t < TT; t++) {
                if (mask & (1u << t)) {
                    const float4 g = sbox[t];
                    const float iw = fminf(ax2, g.z) - fmaxf(ax1, g.x);
                    const float ih = fminf(ay2, g.w) - fmaxf(ay1, g.y);
                    const float inter = fmaxf(iw, 0.f) * fmaxf(ih, 0.f);
                    const float uni = areaA + sarea[t] - inter + 1e-9f;
                    const float iou = __fdividef(inter, uni);
                    if (iou > maxiou) { maxiou = iou; mt = t; }   // first-index tie-break
                    const unsigned long long pk =
                        ((unsigned long long)__float_as_uint(iou) << 32) | nidx;
                    if (pk > s_best[t]) atomicMax(&s_best[t], pk);  // monotone, atomic re-check
                }
            }
        }
        if (valid) {
            unsigned info = (unsigned)mt;
            const bool pos = maxiou >= 0.5f;
            if (pos) info |= 64u;
            if (maxiou < 0.3f) info |= 128u;
            const float x = __ldg(pred + (a3 * 8 + 4) * HW + pix);
            const float bce = fmaxf(x, 0.f) - (pos ? x : 0.f) + __logf(1.f + __expf(-fabsf(x)));
            s_bce[idx]  = bce;
            s_info[idx] = (unsigned char)info;
        }
    }
    __syncthreads();

    // ================= Forced-match overrides (parallel, last-t wins) ====
    if (wid == 0) {
        const bool has = lane < TT;
        unsigned aidx = 0;
        if (has) {
            const unsigned long long v = s_best[lane];
            aidx = ~(unsigned)(v & 0xFFFFFFFFull);
            s_aidx[lane] = aidx;
        }
        __syncwarp();
        bool win = has;
        if (has) {
            for (int t2 = lane + 1; t2 < TT; t2++)
                if (s_aidx[t2] == aidx) win = false;
        }
        if (win) {
            const unsigned old = s_info[aidx];
            if (!(old & 64u)) {                 // newly positive: bce(y=0) -> bce(y=1)
                const int pix = aidx / 3, a3 = aidx - pix * 3;
                s_bce[aidx] -= __ldg(pred + (a3 * 8 + 4) * HW + pix);
            }
            s_info[aidx] = (unsigned char)(lane | 64u);
        }
    }
    __syncthreads();

    // ================= Epilogue: counts, CE + smooth-L1 on positives =====
    // Clobber non-negative keys to 0 so mining needs only s_bce.
    float pos_bce = 0.f, cls_sum = 0.f, loc_sum = 0.f;
    int pos_cnt = 0, neg_cnt = 0;
    for (int idx = tid; idx < A; idx += NT) {
        const unsigned info = s_info[idx];
        if (info & 128u) neg_cnt++;
        else {
            const float bv = s_bce[idx];
            s_bce[idx] = 0.0f;
            if (info & 64u) {
                pos_cnt++;
                pos_bce += bv;
                const int mt = info & 31u;
                const int pix = idx / 3, a3 = idx - pix * 3;
                const float* pp = pred + a3 * 8 * HW + pix;
                const float c0 = pp[5 * HW], c1 = pp[6 * HW], c2 = pp[7 * HW];
                const float m = fmaxf(c0, fmaxf(c1, c2));
                const float lse = m + __logf(__expf(c0 - m) + __expf(c1 - m) + __expf(c2 - m));
                const int tgt = slab[mt] - 1;
                const float ct = (tgt == 0) ? c0 : (tgt == 1) ? c1 : c2;
                cls_sum += lse - ct;

                const int q = pix >> shf;
                const int gy = q / 7;
                const int gx = pix - gy * f;
                const float cx = ((float)gx + 0.5f) * strd;
                const float cy = ((float)gy + 0.5f) * strd;
                const float w = (a3 == 0) ? w0 : (a3 == 1) ? w1 : w2;
                const float4 g = sbox[mt];
                const float gw = g.z - g.x, gh = g.w - g.y;
                const float gcx = (g.x + g.z) * 0.5f, gcy = (g.y + g.w) * 0.5f;
                const float td0 = __fdividef(gcx - cx, w);
                const float td1 = __fdividef(gcy - cy, w);
                const float td2 = __logf(__fdividef(gw, w));
                const float td3 = __logf(__fdividef(gh, w));
                const float d0 = fabsf(pp[0 * HW] - td0);
                const float d1 = fabsf(pp[1 * HW] - td1);
                const float d2 = fabsf(pp[2 * HW] - td2);
                const float d3 = fabsf(pp[3 * HW] - td3);
                loc_sum += (d0 < 1.f ? 0.5f * d0 * d0 : d0 - 0.5f)
                         + (d1 < 1.f ? 0.5f * d1 * d1 : d1 - 0.5f)
                         + (d2 < 1.f ? 0.5f * d2 * d2 : d2 - 0.5f)
                         + (d3 < 1.f ? 0.5f * d3 * d3 : d3 - 0.5f);
            }
        }
    }
    pos_bce = wsum(pos_bce); cls_sum = wsum(cls_sum); loc_sum = wsum(loc_sum);
    pos_cnt = wsumi(pos_cnt); neg_cnt = wsumi(neg_cnt);
    if (lane == 0) {
        atomicAdd(&s_facc[0], pos_bce);
        atomicAdd(&s_facc[1], cls_sum);
        atomicAdd(&s_facc[2], loc_sum);
        atomicAdd(&s_cnt[0], pos_cnt);
        atomicAdd(&s_cnt[1], neg_cnt);
    }
    __syncthreads();
    const int num_pos = s_cnt[0];
    const int num_neg = s_cnt[1];
    const int need = min(3 * num_pos, num_neg);

    // ================= 3-pass radix select (need-th largest key) =========
    float neg_sum = 0.f;
    if (need > 0) {
        int kneed = need;
        unsigned prefix = 0;
        const int shv[3] = {21, 10, 0};
        const int wv[3]  = {11, 11, 10};
#pragma unroll
        for (int p = 0; p < 3; p++) {
            const int sh = shv[p], w = wv[p];
            const int nb = 1 << w;              // 2048, 2048, 1024
            const int gpt = (nb + NT - 1) / NT; // 2, 2, 1
            for (int i = tid; i < nb; i += NT) s_hist[i] = 0;
            __syncthreads();
            for (int idx = tid; idx < A; idx += NT) {
                const unsigned bits = __float_as_uint(s_bce[idx]);
                if (p == 0 || (bits >> (sh + w)) == prefix)
                    atomicAdd(&s_hist[(bits >> sh) & (nb - 1)], 1);
            }
            __syncthreads();
            const int bbase = tid * gpt;
            int h[2]; int local = 0;
#pragma unroll
            for (int j = 0; j < 2; j++) {
                h[j] = (j < gpt && bbase + j < nb) ? s_hist[bbase + j] : 0;
                local += h[j];
            }
            int v = local;                       // inclusive suffix within warp
#pragma unroll
            for (int o = 1; o < 32; o <<= 1) {
                const int u = __shfl_down_sync(0xffffffffu, v, o);
                if (lane + o < 32) v += u;
            }
            if (lane == 0) s_ws[wid] = v;
            __syncthreads();
            if (tid < 32) {
                int x = s_ws[tid];
#pragma unroll
                for (int o = 1; o < 32; o <<= 1) {
                    const int u = __shfl_down_sync(0xffffffffu, x, o);
                    if (tid + o < 32) x += u;
                }
                s_ws[tid] = x;                   // inclusive suffix of warp sums
            }
            __syncthreads();
            int suf = (v - local) + ((wid < 31) ? s_ws[wid + 1] : 0);
#pragma unroll
            for (int j = 1; j >= 0; j--) {
                if (j < gpt && bbase + j < nb) {
                    if (suf < kneed && kneed <= suf + h[j]) { s_selbin = bbase + j; s_Sless = suf; }
                    suf += h[j];
                }
            }
            __syncthreads();
            kneed -= s_Sless;
            prefix = (prefix << w) | (unsigned)s_selbin;
            __syncthreads();
        }
        const unsigned kbits = prefix;           // bits of the need-th largest key
        int cgt = 0; float sgt = 0.f;
        for (int idx = tid; idx < A; idx += NT) {
            const float vv = s_bce[idx];
            if (__float_as_uint(vv) > kbits) { cgt++; sgt += vv; }
        }
        cgt = wsumi(cgt); sgt = wsum(sgt);
        if (lane == 0) { atomicAdd(&s_cnt[2], cgt); atomicAdd(&s_facc[3], sgt); }
        __syncthreads();
        neg_sum = s_facc[3] + (float)(need - s_cnt[2]) * __uint_as_float(kbits);
    }

    if (tid == 0) {
        const float obj_loss = (s_facc[0] + neg_sum) / (float)max(num_pos + need, 1);
        const float cls_loss = s_facc[1] / (float)max(num_pos, 1);
        const float loc_loss = s_facc[2] / (float)max(4 * num_pos, 1);
        g_partial[bid * 3 + 0] = obj_loss;
        g_partial[bid * 3 + 1] = cls_loss;
        g_partial[bid * 3 + 2] = loc_loss;
    }

    // ================= Last-block finalize ================================
    __threadfence();
    if (tid == 0) {
        const int t = atomicAdd(&g_ticket, 1);
        s_flag = (t == NBLK - 1);
    }
    __syncthreads();
    if (s_flag && tid < 32) {
        float o = 0.f, c = 0.f, l = 0.f;
        for (int i = tid; i < NBLK; i += 32) {
            o += g_partial[3 * i + 0];
            c += g_partial[3 * i + 1];
            l += g_partial[3 * i + 2];
        }
        o = wsum(o); c = wsum(c); l = wsum(l);
        if (tid == 0) {
            g_ticket = 0;                        // self-reset for next replay
            o *= (1.f / 64.f); c *= (1.f / 64.f); l *= (1.f / 64.f);
            out[0] = o; out[1] = c; out[2] = l; out[3] = o + c + 2.f * l;
        }
    }
}

extern "C" void kernel_launch(void* const* d_in, const int* in_sizes, int n_in,
                              void* d_out, int out_size) {
    const float* p0 = (const float*)d_in[0];
    const float* p1 = (const float*)d_in[1];
    const float* p2 = (const float*)d_in[2];
    const float* tb = (const float*)d_in[6];
    const int*   tl = (const int*)d_in[7];

    fused_loss<<<NBLK, NT>>>(p0, p1, p2, tb, tl, (float*)d_out);
}